// round 11
// baseline (speedup 1.0000x reference)
#include <cuda_runtime.h>
#include <math.h>

// ---------------------------------------------------------------------------
// Problem constants
// ---------------------------------------------------------------------------
#define NN     1024
#define FF     128
#define MM     256
#define EE     8
#define W1COLS 260           // 2F+4
#define P_TOT  523776        // N*(N-1)/2
#define TI     32            // i tile
#define TJ     16            // j tile
#define WEXTRA 32            // extra floats after W2f: b2f[8], w3[8], b3

typedef unsigned long long ull;

// ---------------------------------------------------------------------------
// Device scratch (no allocations allowed)
// ---------------------------------------------------------------------------
__device__ __align__(16) float g_pa[NN * MM];          // x @ W1a^T
__device__ __align__(16) float g_pb[NN * MM];          // x @ W1b^T
__device__ __align__(16) float g_W2fx[EE * MM + WEXTRA];
__device__ __align__(16) float g_cterm[MM];
__device__ double g_std[NN];
__device__ int    g_stressed[NN];

// Constant copy of folded weights (epilogue scalars + fallback)
__constant__ __align__(16) float c_W2f[EE * MM + WEXTRA];

// ---------------------------------------------------------------------------
// f32x2 packed helpers (FFMA2 path — only reachable via PTX)
// ---------------------------------------------------------------------------
__device__ __forceinline__ ull add2(ull a, ull b) {
    ull r;
    asm("add.rn.f32x2 %0, %1, %2;" : "=l"(r) : "l"(a), "l"(b));
    return r;
}
__device__ __forceinline__ ull fma2(ull a, ull b, ull c) {
    ull r;
    asm("fma.rn.f32x2 %0, %1, %2, %3;" : "=l"(r) : "l"(a), "l"(b), "l"(c));
    return r;
}
__device__ __forceinline__ ull relu2(ull v) {
    float lo = __uint_as_float((unsigned)v);
    float hi = __uint_as_float((unsigned)(v >> 32));
    lo = fmaxf(lo, 0.0f);
    hi = fmaxf(hi, 0.0f);
    return (ull)__float_as_uint(lo) | ((ull)__float_as_uint(hi) << 32);
}

struct __align__(16) F4 { ull lo, hi; };
union U64 { ull u; float2 f; };

// ---------------------------------------------------------------------------
// Stress std: one warp per node, fp64 (a flipped flag is disastrous)
// ---------------------------------------------------------------------------
__global__ void stress_std_kernel(const float* __restrict__ x) {
    int node = blockIdx.x * 4 + (threadIdx.x >> 5);
    int l = threadIdx.x & 31;
    float4 v = *(const float4*)&x[node * FF + l * 4];
    double s  = (double)v.x + (double)v.y + (double)v.z + (double)v.w;
    double s2 = (double)v.x * v.x + (double)v.y * v.y +
                (double)v.z * v.z + (double)v.w * v.w;
    #pragma unroll
    for (int o = 16; o; o >>= 1) {
        s  += __shfl_down_sync(0xffffffffu, s,  o);
        s2 += __shfl_down_sync(0xffffffffu, s2, o);
    }
    if (l == 0) {
        double var = (s2 - s * s / (double)FF) / (double)(FF - 1);
        g_std[node] = sqrt(var > 0.0 ? var : 0.0);
    }
}

// ---------------------------------------------------------------------------
// Prep: stress flags, cterm, BN-fold into W2f/b2f, stash W3/b3
// ---------------------------------------------------------------------------
__global__ void prep_kernel(const float* __restrict__ ctx,
                            const float* __restrict__ W1,
                            const float* __restrict__ b1,
                            const float* __restrict__ gamma,
                            const float* __restrict__ beta,
                            const float* __restrict__ rmean,
                            const float* __restrict__ rvar,
                            const float* __restrict__ W2,
                            const float* __restrict__ b2,
                            const float* __restrict__ W3,
                            const float* __restrict__ b3) {
    int m = threadIdx.x;          // 256 threads
    __shared__ float sbias[MM];
    __shared__ double sred[8];
    __shared__ double smean;

    // ---- stress mean + flags (nodes 4m..4m+3 per thread) ----
    double v0 = g_std[4 * m + 0], v1 = g_std[4 * m + 1];
    double v2 = g_std[4 * m + 2], v3 = g_std[4 * m + 3];
    double s = v0 + v1 + v2 + v3;
    #pragma unroll
    for (int o = 16; o; o >>= 1) s += __shfl_down_sync(0xffffffffu, s, o);
    if ((m & 31) == 0) sred[m >> 5] = s;
    __syncthreads();
    if (m == 0) {
        double u = 0.0;
        #pragma unroll
        for (int w = 0; w < 8; w++) u += sred[w];
        smean = u / (double)NN;
    }
    __syncthreads();
    double mean = smean;
    g_stressed[4 * m + 0] = (v0 > mean) ? 1 : 0;
    g_stressed[4 * m + 1] = (v1 > mean) ? 1 : 0;
    g_stressed[4 * m + 2] = (v2 > mean) ? 1 : 0;
    g_stressed[4 * m + 3] = (v3 > mean) ? 1 : 0;

    // ---- cterm ----
    float ct = b1[m];
    #pragma unroll
    for (int k = 0; k < 4; k++) ct += ctx[k] * W1[m * W1COLS + 2 * FF + k];
    g_cterm[m] = ct;

    // ---- BN fold ----
    float sc = (float)((double)gamma[m] / sqrt((double)rvar[m] + 1e-5));
    float bias = beta[m] - rmean[m] * sc;
    sbias[m] = bias;
    #pragma unroll
    for (int e = 0; e < EE; e++) g_W2fx[e * MM + m] = W2[e * MM + m] * sc;
    __syncthreads();

    int w = m >> 5, l = m & 31;
    if (w < EE) {
        float p = 0.0f;
        for (int mm = l; mm < MM; mm += 32) p += sbias[mm] * W2[w * MM + mm];
        #pragma unroll
        for (int o = 16; o; o >>= 1) p += __shfl_down_sync(0xffffffffu, p, o);
        if (l == 0) g_W2fx[EE * MM + w] = b2[w] + p;
    }
    if (m < EE) g_W2fx[EE * MM + 8 + m] = W3[m];
    if (m == 0) g_W2fx[EE * MM + 16] = b3[0];
    if (m >= 17 && m < WEXTRA) g_W2fx[EE * MM + m] = 0.0f;  // deterministic tail
}

// ---------------------------------------------------------------------------
// GEMM: pa[i,c] = x[i,:]@W1[c,0:128]; pb[i,c] = x[i,:]@W1[c,128:256]
// Tile 128i x 32c, grid (8,16)=128 blocks (single wave), 256 threads.
// ---------------------------------------------------------------------------
__global__ __launch_bounds__(256) void gemm_kernel(const float* __restrict__ x,
                                                   const float* __restrict__ W1) {
    __shared__ float xs[128 * FF];  // 64 KB, swizzled (16B-block XOR with row&7)
    __shared__ float ws[32 * FF];   // 16 KB, linear, read broadcast

    int tid = threadIdx.x;
    int i0 = blockIdx.x * 128;
    int c0 = blockIdx.y * 32;       // c in [0,512): <256 -> pa, else pb

    for (int u = tid; u < 128 * 32; u += 256) {
        int r = u >> 5, q = u & 31;
        *(float4*)&xs[r * FF + ((q ^ (r & 7)) << 2)] =
            *(const float4*)&x[(i0 + r) * FF + q * 4];
    }
    for (int u = tid; u < 32 * 32; u += 256) {
        int r = u >> 5, q = u & 31;
        const float* src = (c0 < MM) ? &W1[(c0 + r) * W1COLS + q * 4]
                                     : &W1[(c0 + r - MM) * W1COLS + FF + q * 4];
        *(float4*)&ws[r * FF + q * 4] = *(const float4*)src;
    }
    __syncthreads();

    int l = tid & 31, w = tid >> 5;           // lane -> i, warp -> 4 c cols
    const char* ax = (const char*)&xs[l * FF];  // rows l, l+32, l+64, l+96
    unsigned xsw = (unsigned)(l & 7) << 4;      // same swizzle for all 4 rows
    const float* bp = &ws[(4 * w) * FF];

    ull acc[4][4];
    #pragma unroll
    for (int r = 0; r < 4; r++)
        #pragma unroll
        for (int c = 0; c < 4; c++) acc[r][c] = 0ull;

    #pragma unroll 4
    for (int k = 0; k < FF; k += 4) {
        unsigned ko = (unsigned)(k << 2) ^ xsw;
        F4 a0 = *(const F4*)(ax + ko);
        F4 a1 = *(const F4*)(ax + 32 * FF * 4 + ko);
        F4 a2 = *(const F4*)(ax + 64 * FF * 4 + ko);
        F4 a3 = *(const F4*)(ax + 96 * FF * 4 + ko);
        F4 b0 = *(const F4*)(bp + k);
        F4 b1 = *(const F4*)(bp + FF + k);
        F4 b2v = *(const F4*)(bp + 2 * FF + k);
        F4 b3v = *(const F4*)(bp + 3 * FF + k);
        acc[0][0] = fma2(a0.lo, b0.lo, acc[0][0]);  acc[0][0] = fma2(a0.hi, b0.hi, acc[0][0]);
        acc[0][1] = fma2(a0.lo, b1.lo, acc[0][1]);  acc[0][1] = fma2(a0.hi, b1.hi, acc[0][1]);
        acc[0][2] = fma2(a0.lo, b2v.lo, acc[0][2]); acc[0][2] = fma2(a0.hi, b2v.hi, acc[0][2]);
        acc[0][3] = fma2(a0.lo, b3v.lo, acc[0][3]); acc[0][3] = fma2(a0.hi, b3v.hi, acc[0][3]);
        acc[1][0] = fma2(a1.lo, b0.lo, acc[1][0]);  acc[1][0] = fma2(a1.hi, b0.hi, acc[1][0]);
        acc[1][1] = fma2(a1.lo, b1.lo, acc[1][1]);  acc[1][1] = fma2(a1.hi, b1.hi, acc[1][1]);
        acc[1][2] = fma2(a1.lo, b2v.lo, acc[1][2]); acc[1][2] = fma2(a1.hi, b2v.hi, acc[1][2]);
        acc[1][3] = fma2(a1.lo, b3v.lo, acc[1][3]); acc[1][3] = fma2(a1.hi, b3v.hi, acc[1][3]);
        acc[2][0] = fma2(a2.lo, b0.lo, acc[2][0]);  acc[2][0] = fma2(a2.hi, b0.hi, acc[2][0]);
        acc[2][1] = fma2(a2.lo, b1.lo, acc[2][1]);  acc[2][1] = fma2(a2.hi, b1.hi, acc[2][1]);
        acc[2][2] = fma2(a2.lo, b2v.lo, acc[2][2]); acc[2][2] = fma2(a2.hi, b2v.hi, acc[2][2]);
        acc[2][3] = fma2(a2.lo, b3v.lo, acc[2][3]); acc[2][3] = fma2(a2.hi, b3v.hi, acc[2][3]);
        acc[3][0] = fma2(a3.lo, b0.lo, acc[3][0]);  acc[3][0] = fma2(a3.hi, b0.hi, acc[3][0]);
        acc[3][1] = fma2(a3.lo, b1.lo, acc[3][1]);  acc[3][1] = fma2(a3.hi, b1.hi, acc[3][1]);
        acc[3][2] = fma2(a3.lo, b2v.lo, acc[3][2]); acc[3][2] = fma2(a3.hi, b2v.hi, acc[3][2]);
        acc[3][3] = fma2(a3.lo, b3v.lo, acc[3][3]); acc[3][3] = fma2(a3.hi, b3v.hi, acc[3][3]);
    }

    #pragma unroll
    for (int ii = 0; ii < 4; ii++) {
        int i = i0 + l + 32 * ii;
        float4 v;
        U64 u0; u0.u = acc[ii][0]; v.x = u0.f.x + u0.f.y;
        U64 u1; u1.u = acc[ii][1]; v.y = u1.f.x + u1.f.y;
        U64 u2; u2.u = acc[ii][2]; v.z = u2.f.x + u2.f.y;
        U64 u3; u3.u = acc[ii][3]; v.w = u3.f.x + u3.f.y;
        if (c0 < MM) *(float4*)&g_pa[i * MM + c0 + 4 * w] = v;
        else         *(float4*)&g_pb[i * MM + (c0 - MM) + 4 * w] = v;
    }
}

// ---------------------------------------------------------------------------
// Pair kernel v2: 32i x 16j tile, 256 threads, 2 pairs/thread (j and j+8).
// acc = 32 regs -> occ 3 without spills. Weights in smem (broadcast LDS,
// avoids the half-rate constant port at 6 warps/SMSP). Pipelined m-loop.
// ---------------------------------------------------------------------------
#define SMEM_PAIR ((TI * MM + TJ * MM + EE * MM) * 4)   // 56 KB

__global__ __launch_bounds__(256, 3) void pair_kernel(float* __restrict__ out,
                                                      int has_mask) {
    extern __shared__ float sm[];
    float* sa = sm;                        // 32 x 256, swizzled (pa + cterm)
    float* sb = sm + TI * MM;              // 16 x 256, swizzled (pb)
    float* sw = sm + (TI + TJ) * MM;       // 8 x 256, linear (broadcast)

    // decode (bi, bj): j-tiles with bj >= 2*bi  (1056 blocks)
    int t = blockIdx.x, bi = 0;
    while (t >= 64 - 2 * bi) { t -= 64 - 2 * bi; bi++; }
    int bj = 2 * bi + t;
    int i0 = bi * TI, j0 = bj * TJ;
    int tid = threadIdx.x;

    // cooperative loads, swizzle on 16B blocks: block q -> q ^ (row & 7)
    for (int u = tid; u < TI * (MM / 4); u += 256) {
        int r = u >> 6, q = u & 63;
        int dst = r * MM + ((q ^ (r & 7)) << 2);
        float4 va = *(const float4*)&g_pa[(i0 + r) * MM + q * 4];
        float4 ct = *(const float4*)&g_cterm[q * 4];
        va.x += ct.x; va.y += ct.y; va.z += ct.z; va.w += ct.w;
        *(float4*)(sa + dst) = va;
    }
    for (int u = tid; u < TJ * (MM / 4); u += 256) {
        int r = u >> 6, q = u & 63;
        int dst = r * MM + ((q ^ (r & 7)) << 2);
        *(float4*)(sb + dst) = *(const float4*)&g_pb[(j0 + r) * MM + q * 4];
    }
    for (int u = tid; u < EE * (MM / 4); u += 256) {
        *(float4*)(sw + u * 4) = *(const float4*)&g_W2fx[u * 4];
    }
    __syncthreads();

    int li = tid >> 3;            // 0..31  (i row; 8-lane broadcast on loads)
    int lj = tid & 7;             // 0..7   (j rows lj and lj+8)
    const char* pA  = (const char*)(sa + li * MM);
    const char* pB0 = (const char*)(sb + lj * MM);
    const char* pB1 = (const char*)(sb + (lj + 8) * MM);
    unsigned xa = (unsigned)(li & 7) << 4;
    unsigned xb = (unsigned)lj << 4;       // (lj+8)&7 == lj -> same swizzle

    ull acc[2][EE];
    #pragma unroll
    for (int p = 0; p < 2; p++)
        #pragma unroll
        for (int e = 0; e < EE; e++) acc[p][e] = 0ull;

    // prologue
    F4 A  = *(const F4*)(pA  + (0u ^ xa));
    F4 B0 = *(const F4*)(pB0 + (0u ^ xb));
    F4 B1 = *(const F4*)(pB1 + (0u ^ xb));

    #pragma unroll 1
    for (int m = 0; m < MM; m += 4) {
        unsigned mn = (unsigned)(((m + 4) & (MM - 1)) << 2);
        F4 nA  = *(const F4*)(pA  + (mn ^ xa));
        F4 nB0 = *(const F4*)(pB0 + (mn ^ xb));
        F4 nB1 = *(const F4*)(pB1 + (mn ^ xb));

        ull rl0 = relu2(add2(A.lo, B0.lo));
        ull rl1 = relu2(add2(A.lo, B1.lo));
        ull rh0 = relu2(add2(A.hi, B0.hi));
        ull rh1 = relu2(add2(A.hi, B1.hi));

        #pragma unroll
        for (int e = 0; e < EE; e++) {
            F4 w = *(const F4*)(sw + e * MM + m);   // uniform -> broadcast
            acc[0][e] = fma2(rl0, w.lo, acc[0][e]);
            acc[1][e] = fma2(rl1, w.lo, acc[1][e]);
            acc[0][e] = fma2(rh0, w.hi, acc[0][e]);
            acc[1][e] = fma2(rh1, w.hi, acc[1][e]);
        }

        A = nA; B0 = nB0; B1 = nB1;
    }

    // epilogue (scalars from constant memory)
    float vb2[EE], vw3[EE];
    #pragma unroll
    for (int e = 0; e < EE; e++) {
        vb2[e] = c_W2f[EE * MM + e];
        vw3[e] = c_W2f[EE * MM + 8 + e];
    }
    float bb3 = c_W2f[EE * MM + 16];

    int i = i0 + li;
    #pragma unroll
    for (int p = 0; p < 2; p++) {
        int j = j0 + lj + 8 * p;
        if (j <= i) continue;
        float z = bb3;
        #pragma unroll
        for (int e = 0; e < EE; e++) {
            U64 u; u.u = acc[p][e];
            float h = u.f.x + u.f.y + vb2[e];
            h = fmaxf(h, 0.0f);
            z = fmaf(h, vw3[e], z);
        }
        float s = 1.0f / (1.0f + expf(-z));
        unsigned pidx = (unsigned)(i * (2 * NN - i - 1) / 2 + (j - i - 1));
        out[pidx] = s;
        if (has_mask) {
            bool msk = (s > 0.5f) && g_stressed[i] && g_stressed[j];
            out[P_TOT + pidx] = msk ? 1.0f : 0.0f;
        }
    }
}

// ---------------------------------------------------------------------------
// Launch
// ---------------------------------------------------------------------------
extern "C" void kernel_launch(void* const* d_in, const int* in_sizes, int n_in,
                              void* d_out, int out_size) {
    const float* x     = (const float*)d_in[0];
    const float* ctx   = (const float*)d_in[1];
    const float* W1    = (const float*)d_in[2];
    const float* b1    = (const float*)d_in[3];
    const float* gamma = (const float*)d_in[4];
    const float* beta  = (const float*)d_in[5];
    const float* rmean = (const float*)d_in[6];
    const float* rvar  = (const float*)d_in[7];
    const float* W2    = (const float*)d_in[8];
    const float* b2    = (const float*)d_in[9];
    const float* W3    = (const float*)d_in[10];
    const float* b3    = (const float*)d_in[11];
    float* out = (float*)d_out;

    (void)in_sizes; (void)n_in;

    static void* w2f_dev = 0;
    if (!w2f_dev) {
        cudaFuncSetAttribute(pair_kernel,
                             cudaFuncAttributeMaxDynamicSharedMemorySize, SMEM_PAIR);
        cudaGetSymbolAddress(&w2f_dev, g_W2fx);
    }

    gemm_kernel<<<dim3(NN / 128, 512 / 32), 256>>>(x, W1);
    stress_std_kernel<<<NN / 4, 128>>>(x);
    prep_kernel<<<1, MM>>>(ctx, W1, b1, gamma, beta, rmean, rvar, W2, b2, W3, b3);
    cudaMemcpyToSymbolAsync(c_W2f, w2f_dev, (EE * MM + WEXTRA) * sizeof(float),
                            0, cudaMemcpyDeviceToDevice, 0);

    int has_mask = (out_size >= 2 * P_TOT) ? 1 : 0;
    pair_kernel<<<1056, 256, SMEM_PAIR>>>(out, has_mask);
}

// round 13
// speedup vs baseline: 1.0173x; 1.0173x over previous
#include <cuda_runtime.h>
#include <math.h>

// ---------------------------------------------------------------------------
// Problem constants
// ---------------------------------------------------------------------------
#define NN     1024
#define FF     128
#define MM     256
#define EE     8
#define W1COLS 260           // 2F+4
#define P_TOT  523776        // N*(N-1)/2
#define TILE   32            // i/j tile per block
#define NTILE  32            // N / TILE
#define WEXTRA 32            // extra floats after W2f: b2f[8], w3[8], b3
#define WTOT   (EE * MM + WEXTRA)

typedef unsigned long long ull;

// ---------------------------------------------------------------------------
// Device scratch (no allocations allowed)
// ---------------------------------------------------------------------------
__device__ __align__(16) float g_pa[NN * MM];          // x @ W1a^T
__device__ __align__(16) float g_pb[NN * MM];          // x @ W1b^T
__device__ __align__(16) float g_W2fx[WTOT];           // folded W2 + b2f/w3/b3
__device__ __align__(16) float g_cterm[MM];
__device__ double g_std[NN];
__device__ int    g_stressed[NN];

// ---------------------------------------------------------------------------
// f32x2 packed helpers (FFMA2 path — only reachable via PTX)
// ---------------------------------------------------------------------------
__device__ __forceinline__ ull add2(ull a, ull b) {
    ull r;
    asm("add.rn.f32x2 %0, %1, %2;" : "=l"(r) : "l"(a), "l"(b));
    return r;
}
__device__ __forceinline__ ull fma2(ull a, ull b, ull c) {
    ull r;
    asm("fma.rn.f32x2 %0, %1, %2, %3;" : "=l"(r) : "l"(a), "l"(b), "l"(c));
    return r;
}
__device__ __forceinline__ ull relu2(ull v) {
    float lo = __uint_as_float((unsigned)v);
    float hi = __uint_as_float((unsigned)(v >> 32));
    lo = fmaxf(lo, 0.0f);
    hi = fmaxf(hi, 0.0f);
    return (ull)__float_as_uint(lo) | ((ull)__float_as_uint(hi) << 32);
}

struct __align__(16) F4 { ull lo, hi; };
union U64 { ull u; float2 f; };

// ---------------------------------------------------------------------------
// Stress std: one warp per node, fp64 (a flipped flag is disastrous)
// ---------------------------------------------------------------------------
__global__ void stress_std_kernel(const float* __restrict__ x) {
    int node = blockIdx.x * 4 + (threadIdx.x >> 5);
    int l = threadIdx.x & 31;
    float4 v = *(const float4*)&x[node * FF + l * 4];
    double s  = (double)v.x + (double)v.y + (double)v.z + (double)v.w;
    double s2 = (double)v.x * v.x + (double)v.y * v.y +
                (double)v.z * v.z + (double)v.w * v.w;
    #pragma unroll
    for (int o = 16; o; o >>= 1) {
        s  += __shfl_down_sync(0xffffffffu, s,  o);
        s2 += __shfl_down_sync(0xffffffffu, s2, o);
    }
    if (l == 0) {
        double var = (s2 - s * s / (double)FF) / (double)(FF - 1);
        g_std[node] = sqrt(var > 0.0 ? var : 0.0);
    }
}

// ---------------------------------------------------------------------------
// Prep: stress flags, cterm, BN-fold into W2f/b2f, stash W3/b3
// ---------------------------------------------------------------------------
__global__ void prep_kernel(const float* __restrict__ ctx,
                            const float* __restrict__ W1,
                            const float* __restrict__ b1,
                            const float* __restrict__ gamma,
                            const float* __restrict__ beta,
                            const float* __restrict__ rmean,
                            const float* __restrict__ rvar,
                            const float* __restrict__ W2,
                            const float* __restrict__ b2,
                            const float* __restrict__ W3,
                            const float* __restrict__ b3) {
    int m = threadIdx.x;          // 256 threads
    __shared__ float sbias[MM];
    __shared__ double sred[8];
    __shared__ double smean;

    // ---- stress mean + flags (nodes 4m..4m+3 per thread) ----
    double v0 = g_std[4 * m + 0], v1 = g_std[4 * m + 1];
    double v2 = g_std[4 * m + 2], v3 = g_std[4 * m + 3];
    double s = v0 + v1 + v2 + v3;
    #pragma unroll
    for (int o = 16; o; o >>= 1) s += __shfl_down_sync(0xffffffffu, s, o);
    if ((m & 31) == 0) sred[m >> 5] = s;
    __syncthreads();
    if (m == 0) {
        double u = 0.0;
        #pragma unroll
        for (int w = 0; w < 8; w++) u += sred[w];
        smean = u / (double)NN;
    }
    __syncthreads();
    double mean = smean;
    g_stressed[4 * m + 0] = (v0 > mean) ? 1 : 0;
    g_stressed[4 * m + 1] = (v1 > mean) ? 1 : 0;
    g_stressed[4 * m + 2] = (v2 > mean) ? 1 : 0;
    g_stressed[4 * m + 3] = (v3 > mean) ? 1 : 0;

    // ---- cterm ----
    float ct = b1[m];
    #pragma unroll
    for (int k = 0; k < 4; k++) ct += ctx[k] * W1[m * W1COLS + 2 * FF + k];
    g_cterm[m] = ct;

    // ---- BN fold ----
    float sc = (float)((double)gamma[m] / sqrt((double)rvar[m] + 1e-5));
    float bias = beta[m] - rmean[m] * sc;
    sbias[m] = bias;
    #pragma unroll
    for (int e = 0; e < EE; e++) g_W2fx[e * MM + m] = W2[e * MM + m] * sc;
    __syncthreads();

    int w = m >> 5, l = m & 31;
    if (w < EE) {
        float p = 0.0f;
        for (int mm = l; mm < MM; mm += 32) p += sbias[mm] * W2[w * MM + mm];
        #pragma unroll
        for (int o = 16; o; o >>= 1) p += __shfl_down_sync(0xffffffffu, p, o);
        if (l == 0) g_W2fx[EE * MM + w] = b2[w] + p;
    }
    if (m < EE) g_W2fx[EE * MM + 8 + m] = W3[m];
    if (m == 0) g_W2fx[EE * MM + 16] = b3[0];
    if (m >= 17 && m < WEXTRA) g_W2fx[EE * MM + m] = 0.0f;  // deterministic tail
}

// ---------------------------------------------------------------------------
// GEMM: pa[i,c] = x[i,:]@W1[c,0:128]; pb[i,c] = x[i,:]@W1[c,128:256]
// Tile 128i x 32c, grid (8,16)=128 blocks (single wave), 256 threads.
// ---------------------------------------------------------------------------
__global__ __launch_bounds__(256) void gemm_kernel(const float* __restrict__ x,
                                                   const float* __restrict__ W1) {
    __shared__ float xs[128 * FF];  // 64 KB, swizzled (16B-block XOR with row&7)
    __shared__ float ws[32 * FF];   // 16 KB, linear, read broadcast

    int tid = threadIdx.x;
    int i0 = blockIdx.x * 128;
    int c0 = blockIdx.y * 32;       // c in [0,512): <256 -> pa, else pb

    for (int u = tid; u < 128 * 32; u += 256) {
        int r = u >> 5, q = u & 31;
        *(float4*)&xs[r * FF + ((q ^ (r & 7)) << 2)] =
            *(const float4*)&x[(i0 + r) * FF + q * 4];
    }
    for (int u = tid; u < 32 * 32; u += 256) {
        int r = u >> 5, q = u & 31;
        const float* src = (c0 < MM) ? &W1[(c0 + r) * W1COLS + q * 4]
                                     : &W1[(c0 + r - MM) * W1COLS + FF + q * 4];
        *(float4*)&ws[r * FF + q * 4] = *(const float4*)src;
    }
    __syncthreads();

    int l = tid & 31, w = tid >> 5;           // lane -> i, warp -> 4 c cols
    const char* ax = (const char*)&xs[l * FF];  // rows l, l+32, l+64, l+96
    unsigned xsw = (unsigned)(l & 7) << 4;      // same swizzle for all 4 rows
    const float* bp = &ws[(4 * w) * FF];

    ull acc[4][4];
    #pragma unroll
    for (int r = 0; r < 4; r++)
        #pragma unroll
        for (int c = 0; c < 4; c++) acc[r][c] = 0ull;

    #pragma unroll 4
    for (int k = 0; k < FF; k += 4) {
        unsigned ko = (unsigned)(k << 2) ^ xsw;
        F4 a0 = *(const F4*)(ax + ko);
        F4 a1 = *(const F4*)(ax + 32 * FF * 4 + ko);
        F4 a2 = *(const F4*)(ax + 64 * FF * 4 + ko);
        F4 a3 = *(const F4*)(ax + 96 * FF * 4 + ko);
        F4 b0 = *(const F4*)(bp + k);
        F4 b1 = *(const F4*)(bp + FF + k);
        F4 b2v = *(const F4*)(bp + 2 * FF + k);
        F4 b3v = *(const F4*)(bp + 3 * FF + k);
        acc[0][0] = fma2(a0.lo, b0.lo, acc[0][0]);  acc[0][0] = fma2(a0.hi, b0.hi, acc[0][0]);
        acc[0][1] = fma2(a0.lo, b1.lo, acc[0][1]);  acc[0][1] = fma2(a0.hi, b1.hi, acc[0][1]);
        acc[0][2] = fma2(a0.lo, b2v.lo, acc[0][2]); acc[0][2] = fma2(a0.hi, b2v.hi, acc[0][2]);
        acc[0][3] = fma2(a0.lo, b3v.lo, acc[0][3]); acc[0][3] = fma2(a0.hi, b3v.hi, acc[0][3]);
        acc[1][0] = fma2(a1.lo, b0.lo, acc[1][0]);  acc[1][0] = fma2(a1.hi, b0.hi, acc[1][0]);
        acc[1][1] = fma2(a1.lo, b1.lo, acc[1][1]);  acc[1][1] = fma2(a1.hi, b1.hi, acc[1][1]);
        acc[1][2] = fma2(a1.lo, b2v.lo, acc[1][2]); acc[1][2] = fma2(a1.hi, b2v.hi, acc[1][2]);
        acc[1][3] = fma2(a1.lo, b3v.lo, acc[1][3]); acc[1][3] = fma2(a1.hi, b3v.hi, acc[1][3]);
        acc[2][0] = fma2(a2.lo, b0.lo, acc[2][0]);  acc[2][0] = fma2(a2.hi, b0.hi, acc[2][0]);
        acc[2][1] = fma2(a2.lo, b1.lo, acc[2][1]);  acc[2][1] = fma2(a2.hi, b1.hi, acc[2][1]);
        acc[2][2] = fma2(a2.lo, b2v.lo, acc[2][2]); acc[2][2] = fma2(a2.hi, b2v.hi, acc[2][2]);
        acc[2][3] = fma2(a2.lo, b3v.lo, acc[2][3]); acc[2][3] = fma2(a2.hi, b3v.hi, acc[2][3]);
        acc[3][0] = fma2(a3.lo, b0.lo, acc[3][0]);  acc[3][0] = fma2(a3.hi, b0.hi, acc[3][0]);
        acc[3][1] = fma2(a3.lo, b1.lo, acc[3][1]);  acc[3][1] = fma2(a3.hi, b1.hi, acc[3][1]);
        acc[3][2] = fma2(a3.lo, b2v.lo, acc[3][2]); acc[3][2] = fma2(a3.hi, b2v.hi, acc[3][2]);
        acc[3][3] = fma2(a3.lo, b3v.lo, acc[3][3]); acc[3][3] = fma2(a3.hi, b3v.hi, acc[3][3]);
    }

    #pragma unroll
    for (int ii = 0; ii < 4; ii++) {
        int i = i0 + l + 32 * ii;
        float4 v;
        U64 u0; u0.u = acc[ii][0]; v.x = u0.f.x + u0.f.y;
        U64 u1; u1.u = acc[ii][1]; v.y = u1.f.x + u1.f.y;
        U64 u2; u2.u = acc[ii][2]; v.z = u2.f.x + u2.f.y;
        U64 u3; u3.u = acc[ii][3]; v.w = u3.f.x + u3.f.y;
        if (c0 < MM) *(float4*)&g_pa[i * MM + c0 + 4 * w] = v;
        else         *(float4*)&g_pb[i * MM + (c0 - MM) + 4 * w] = v;
    }
}

// ---------------------------------------------------------------------------
// Pair kernel (R10 shape): 32i x 32j tile, 256 threads, 2x2 pairs/thread
// (rows r, r+16), XOR-swizzled smem, pipelined m-loop.
// CHANGE vs R10: weights read from SMEM broadcast (uniform LDS) instead of
// __constant__ — the half-rate constant port (LDC->LDC floor 8/SMSP) was
// binding at 32 LDC.128 per SMSP round-set.
// ---------------------------------------------------------------------------
#define SMEM_PAIR ((2 * TILE * MM + WTOT) * 4)   // ~72 KB

__global__ __launch_bounds__(256, 2) void pair_kernel(float* __restrict__ out,
                                                      int has_mask) {
    extern __shared__ float sm[];
    float* sa = sm;                        // 32 x 256, swizzled (pa + cterm)
    float* sb = sm + TILE * MM;            // 32 x 256, swizzled (pb)
    float* sw = sm + 2 * TILE * MM;        // WTOT, linear (broadcast reads)

    // decode (bi, bj), bi <= bj
    int t = blockIdx.x, bi = 0;
    while (t >= NTILE - bi) { t -= NTILE - bi; bi++; }
    int bj = bi + t;
    int i0 = bi * TILE, j0 = bj * TILE;
    int tid = threadIdx.x;

    // cooperative loads, swizzle on 16B blocks: block q -> q ^ (row & 7)
    for (int u = tid; u < TILE * (MM / 4); u += 256) {
        int r = u >> 6, q = u & 63;
        int dst = r * MM + ((q ^ (r & 7)) << 2);
        float4 va = *(const float4*)&g_pa[(i0 + r) * MM + q * 4];
        float4 ct = *(const float4*)&g_cterm[q * 4];
        va.x += ct.x; va.y += ct.y; va.z += ct.z; va.w += ct.w;
        *(float4*)(sa + dst) = va;
        *(float4*)(sb + dst) = *(const float4*)&g_pb[(j0 + r) * MM + q * 4];
    }
    for (int u = tid; u < WTOT / 4; u += 256) {
        *(float4*)(sw + u * 4) = *(const float4*)&g_W2fx[u * 4];
    }
    __syncthreads();

    int ti2 = tid >> 4, tj2 = tid & 15;
    int rA = ti2, rB = ti2 + 16;          // i rows
    int sA = tj2, sB = tj2 + 16;          // j rows
    const char* pa0 = (const char*)(sa + rA * MM);
    const char* pa1 = (const char*)(sa + rB * MM);
    const char* pb0 = (const char*)(sb + sA * MM);
    const char* pb1 = (const char*)(sb + sB * MM);
    unsigned xa0 = (unsigned)(rA & 7) << 4;
    unsigned xa1 = (unsigned)(rB & 7) << 4;
    unsigned xb0 = (unsigned)(sA & 7) << 4;
    unsigned xb1 = (unsigned)(sB & 7) << 4;

    ull acc[4][EE];
    #pragma unroll
    for (int p = 0; p < 4; p++)
        #pragma unroll
        for (int e = 0; e < EE; e++) acc[p][e] = 0ull;

    // prologue: load round 0
    F4 a0 = *(const F4*)(pa0 + (0u ^ xa0));
    F4 a1 = *(const F4*)(pa1 + (0u ^ xa1));
    F4 b0 = *(const F4*)(pb0 + (0u ^ xb0));
    F4 b1 = *(const F4*)(pb1 + (0u ^ xb1));

    #pragma unroll 1
    for (int m = 0; m < MM; m += 4) {
        // prefetch next round (wraps to 0 on last iter — harmless re-read)
        unsigned mn = (unsigned)(((m + 4) & (MM - 1)) << 2);
        F4 na0 = *(const F4*)(pa0 + (mn ^ xa0));
        F4 na1 = *(const F4*)(pa1 + (mn ^ xa1));
        F4 nb0 = *(const F4*)(pb0 + (mn ^ xb0));
        F4 nb1 = *(const F4*)(pb1 + (mn ^ xb1));

        ull rl0 = relu2(add2(a0.lo, b0.lo));
        ull rl1 = relu2(add2(a0.lo, b1.lo));
        ull rl2 = relu2(add2(a1.lo, b0.lo));
        ull rl3 = relu2(add2(a1.lo, b1.lo));
        ull rh0 = relu2(add2(a0.hi, b0.hi));
        ull rh1 = relu2(add2(a0.hi, b1.hi));
        ull rh2 = relu2(add2(a1.hi, b0.hi));
        ull rh3 = relu2(add2(a1.hi, b1.hi));

        #pragma unroll
        for (int e = 0; e < EE; e++) {
            F4 w = *(const F4*)(sw + e * MM + m);  // uniform -> smem broadcast
            acc[0][e] = fma2(rl0, w.lo, acc[0][e]);
            acc[1][e] = fma2(rl1, w.lo, acc[1][e]);
            acc[2][e] = fma2(rl2, w.lo, acc[2][e]);
            acc[3][e] = fma2(rl3, w.lo, acc[3][e]);
            acc[0][e] = fma2(rh0, w.hi, acc[0][e]);
            acc[1][e] = fma2(rh1, w.hi, acc[1][e]);
            acc[2][e] = fma2(rh2, w.hi, acc[2][e]);
            acc[3][e] = fma2(rh3, w.hi, acc[3][e]);
        }

        a0 = na0; a1 = na1; b0 = nb0; b1 = nb1;
    }

    // epilogue (scalars from smem)
    float vb2[EE], vw3[EE];
    #pragma unroll
    for (int e = 0; e < EE; e++) {
        vb2[e] = sw[EE * MM + e];
        vw3[e] = sw[EE * MM + 8 + e];
    }
    float bb3 = sw[EE * MM + 16];

    int li[4] = { rA, rA, rB, rB };
    int lj[4] = { sA, sB, sA, sB };
    #pragma unroll
    for (int p = 0; p < 4; p++) {
        int i = i0 + li[p], j = j0 + lj[p];
        if (j <= i) continue;
        float z = bb3;
        #pragma unroll
        for (int e = 0; e < EE; e++) {
            U64 u; u.u = acc[p][e];
            float h = u.f.x + u.f.y + vb2[e];
            h = fmaxf(h, 0.0f);
            z = fmaf(h, vw3[e], z);
        }
        float s = 1.0f / (1.0f + expf(-z));
        unsigned pidx = (unsigned)(i * (2 * NN - i - 1) / 2 + (j - i - 1));
        out[pidx] = s;
        if (has_mask) {
            bool msk = (s > 0.5f) && g_stressed[i] && g_stressed[j];
            out[P_TOT + pidx] = msk ? 1.0f : 0.0f;
        }
    }
}

// ---------------------------------------------------------------------------
// Launch: side-stream overlap of stress/prep with gemm (event fork/join,
// graph-capturable). pair waits on both.
// ---------------------------------------------------------------------------
extern "C" void kernel_launch(void* const* d_in, const int* in_sizes, int n_in,
                              void* d_out, int out_size) {
    const float* x     = (const float*)d_in[0];
    const float* ctx   = (const float*)d_in[1];
    const float* W1    = (const float*)d_in[2];
    const float* b1    = (const float*)d_in[3];
    const float* gamma = (const float*)d_in[4];
    const float* beta  = (const float*)d_in[5];
    const float* rmean = (const float*)d_in[6];
    const float* rvar  = (const float*)d_in[7];
    const float* W2    = (const float*)d_in[8];
    const float* b2    = (const float*)d_in[9];
    const float* W3    = (const float*)d_in[10];
    const float* b3    = (const float*)d_in[11];
    float* out = (float*)d_out;

    (void)in_sizes; (void)n_in;

    static cudaStream_t s1 = 0;
    static cudaEvent_t e0 = 0, e1 = 0;
    if (!s1) {
        cudaStreamCreateWithFlags(&s1, cudaStreamNonBlocking);
        cudaEventCreateWithFlags(&e0, cudaEventDisableTiming);
        cudaEventCreateWithFlags(&e1, cudaEventDisableTiming);
        cudaFuncSetAttribute(pair_kernel,
                             cudaFuncAttributeMaxDynamicSharedMemorySize, SMEM_PAIR);
    }

    // fork: side stream does stress + prep while main stream does gemm
    cudaEventRecord(e0, 0);
    cudaStreamWaitEvent(s1, e0, 0);
    stress_std_kernel<<<NN / 4, 128, 0, s1>>>(x);
    prep_kernel<<<1, MM, 0, s1>>>(ctx, W1, b1, gamma, beta, rmean, rvar,
                                  W2, b2, W3, b3);
    cudaEventRecord(e1, s1);

    gemm_kernel<<<dim3(NN / 128, 512 / 32), 256>>>(x, W1);

    // join
    cudaStreamWaitEvent(0, e1, 0);

    int has_mask = (out_size >= 2 * P_TOT) ? 1 : 0;
    int nblocks = NTILE * (NTILE + 1) / 2;   // 528
    pair_kernel<<<nblocks, 256, SMEM_PAIR>>>(out, has_mask);
}

// round 14
// speedup vs baseline: 1.2148x; 1.1942x over previous
#include <cuda_runtime.h>
#include <math.h>

// ---------------------------------------------------------------------------
// Problem constants
// ---------------------------------------------------------------------------
#define NN     1024
#define FF     128
#define MM     256
#define EE     8
#define W1COLS 260           // 2F+4
#define P_TOT  523776        // N*(N-1)/2
#define TILE   32            // i/j tile per block
#define NTILE  32            // N / TILE
#define WEXTRA 32            // extra floats after W2f: b2f[8], w3[8], b3
#define WTOT   (EE * MM + WEXTRA)

typedef unsigned long long ull;

// ---------------------------------------------------------------------------
// Device scratch (no allocations allowed)
// ---------------------------------------------------------------------------
__device__ __align__(16) float g_pa[NN * MM];          // x @ W1a^T
__device__ __align__(16) float g_pb[NN * MM];          // x @ W1b^T
__device__ __align__(16) float g_W2fx[WTOT];           // folded W2 + b2f/w3/b3
__device__ __align__(16) float g_cterm[MM];
__device__ double g_std[NN];
__device__ int    g_stressed[NN];

// Constant copy of folded weights (filled by async D2D memcpy each call).
// R13 disproved the "constant port is binding" theory — LDC weights are the
// fastest measured variant (R10).
__constant__ __align__(16) float c_W2f[WTOT];

// ---------------------------------------------------------------------------
// f32x2 packed helpers (FFMA2 path — only reachable via PTX)
// ---------------------------------------------------------------------------
__device__ __forceinline__ ull add2(ull a, ull b) {
    ull r;
    asm("add.rn.f32x2 %0, %1, %2;" : "=l"(r) : "l"(a), "l"(b));
    return r;
}
__device__ __forceinline__ ull fma2(ull a, ull b, ull c) {
    ull r;
    asm("fma.rn.f32x2 %0, %1, %2, %3;" : "=l"(r) : "l"(a), "l"(b), "l"(c));
    return r;
}
__device__ __forceinline__ ull relu2(ull v) {
    float lo = __uint_as_float((unsigned)v);
    float hi = __uint_as_float((unsigned)(v >> 32));
    lo = fmaxf(lo, 0.0f);
    hi = fmaxf(hi, 0.0f);
    return (ull)__float_as_uint(lo) | ((ull)__float_as_uint(hi) << 32);
}

struct __align__(16) F4 { ull lo, hi; };
union U64 { ull u; float2 f; };

// ---------------------------------------------------------------------------
// Stress std: one warp per node, fp64 (a flipped flag is disastrous)
// ---------------------------------------------------------------------------
__global__ void stress_std_kernel(const float* __restrict__ x) {
    int node = blockIdx.x * 4 + (threadIdx.x >> 5);
    int l = threadIdx.x & 31;
    float4 v = *(const float4*)&x[node * FF + l * 4];
    double s  = (double)v.x + (double)v.y + (double)v.z + (double)v.w;
    double s2 = (double)v.x * v.x + (double)v.y * v.y +
                (double)v.z * v.z + (double)v.w * v.w;
    #pragma unroll
    for (int o = 16; o; o >>= 1) {
        s  += __shfl_down_sync(0xffffffffu, s,  o);
        s2 += __shfl_down_sync(0xffffffffu, s2, o);
    }
    if (l == 0) {
        double var = (s2 - s * s / (double)FF) / (double)(FF - 1);
        g_std[node] = sqrt(var > 0.0 ? var : 0.0);
    }
}

// ---------------------------------------------------------------------------
// Prep: stress flags, cterm, BN-fold into W2f/b2f, stash W3/b3
// ---------------------------------------------------------------------------
__global__ void prep_kernel(const float* __restrict__ ctx,
                            const float* __restrict__ W1,
                            const float* __restrict__ b1,
                            const float* __restrict__ gamma,
                            const float* __restrict__ beta,
                            const float* __restrict__ rmean,
                            const float* __restrict__ rvar,
                            const float* __restrict__ W2,
                            const float* __restrict__ b2,
                            const float* __restrict__ W3,
                            const float* __restrict__ b3) {
    int m = threadIdx.x;          // 256 threads
    __shared__ float sbias[MM];
    __shared__ double sred[8];
    __shared__ double smean;

    // ---- stress mean + flags (nodes 4m..4m+3 per thread) ----
    double v0 = g_std[4 * m + 0], v1 = g_std[4 * m + 1];
    double v2 = g_std[4 * m + 2], v3 = g_std[4 * m + 3];
    double s = v0 + v1 + v2 + v3;
    #pragma unroll
    for (int o = 16; o; o >>= 1) s += __shfl_down_sync(0xffffffffu, s, o);
    if ((m & 31) == 0) sred[m >> 5] = s;
    __syncthreads();
    if (m == 0) {
        double u = 0.0;
        #pragma unroll
        for (int w = 0; w < 8; w++) u += sred[w];
        smean = u / (double)NN;
    }
    __syncthreads();
    double mean = smean;
    g_stressed[4 * m + 0] = (v0 > mean) ? 1 : 0;
    g_stressed[4 * m + 1] = (v1 > mean) ? 1 : 0;
    g_stressed[4 * m + 2] = (v2 > mean) ? 1 : 0;
    g_stressed[4 * m + 3] = (v3 > mean) ? 1 : 0;

    // ---- cterm ----
    float ct = b1[m];
    #pragma unroll
    for (int k = 0; k < 4; k++) ct += ctx[k] * W1[m * W1COLS + 2 * FF + k];
    g_cterm[m] = ct;

    // ---- BN fold ----
    float sc = (float)((double)gamma[m] / sqrt((double)rvar[m] + 1e-5));
    float bias = beta[m] - rmean[m] * sc;
    sbias[m] = bias;
    #pragma unroll
    for (int e = 0; e < EE; e++) g_W2fx[e * MM + m] = W2[e * MM + m] * sc;
    __syncthreads();

    int w = m >> 5, l = m & 31;
    if (w < EE) {
        float p = 0.0f;
        for (int mm = l; mm < MM; mm += 32) p += sbias[mm] * W2[w * MM + mm];
        #pragma unroll
        for (int o = 16; o; o >>= 1) p += __shfl_down_sync(0xffffffffu, p, o);
        if (l == 0) g_W2fx[EE * MM + w] = b2[w] + p;
    }
    if (m < EE) g_W2fx[EE * MM + 8 + m] = W3[m];
    if (m == 0) g_W2fx[EE * MM + 16] = b3[0];
    if (m >= 17 && m < WEXTRA) g_W2fx[EE * MM + m] = 0.0f;  // deterministic tail
}

// ---------------------------------------------------------------------------
// GEMM: pa[i,c] = x[i,:]@W1[c,0:128]; pb[i,c] = x[i,:]@W1[c,128:256]
// Tile 128i x 32c, grid (8,16)=128 blocks (single wave), 256 threads.
// ---------------------------------------------------------------------------
__global__ __launch_bounds__(256) void gemm_kernel(const float* __restrict__ x,
                                                   const float* __restrict__ W1) {
    __shared__ float xs[128 * FF];  // 64 KB, swizzled (16B-block XOR with row&7)
    __shared__ float ws[32 * FF];   // 16 KB, linear, read broadcast

    int tid = threadIdx.x;
    int i0 = blockIdx.x * 128;
    int c0 = blockIdx.y * 32;       // c in [0,512): <256 -> pa, else pb

    for (int u = tid; u < 128 * 32; u += 256) {
        int r = u >> 5, q = u & 31;
        *(float4*)&xs[r * FF + ((q ^ (r & 7)) << 2)] =
            *(const float4*)&x[(i0 + r) * FF + q * 4];
    }
    for (int u = tid; u < 32 * 32; u += 256) {
        int r = u >> 5, q = u & 31;
        const float* src = (c0 < MM) ? &W1[(c0 + r) * W1COLS + q * 4]
                                     : &W1[(c0 + r - MM) * W1COLS + FF + q * 4];
        *(float4*)&ws[r * FF + q * 4] = *(const float4*)src;
    }
    __syncthreads();

    int l = tid & 31, w = tid >> 5;           // lane -> i, warp -> 4 c cols
    const char* ax = (const char*)&xs[l * FF];  // rows l, l+32, l+64, l+96
    unsigned xsw = (unsigned)(l & 7) << 4;      // same swizzle for all 4 rows
    const float* bp = &ws[(4 * w) * FF];

    ull acc[4][4];
    #pragma unroll
    for (int r = 0; r < 4; r++)
        #pragma unroll
        for (int c = 0; c < 4; c++) acc[r][c] = 0ull;

    #pragma unroll 4
    for (int k = 0; k < FF; k += 4) {
        unsigned ko = (unsigned)(k << 2) ^ xsw;
        F4 a0 = *(const F4*)(ax + ko);
        F4 a1 = *(const F4*)(ax + 32 * FF * 4 + ko);
        F4 a2 = *(const F4*)(ax + 64 * FF * 4 + ko);
        F4 a3 = *(const F4*)(ax + 96 * FF * 4 + ko);
        F4 b0 = *(const F4*)(bp + k);
        F4 b1 = *(const F4*)(bp + FF + k);
        F4 b2v = *(const F4*)(bp + 2 * FF + k);
        F4 b3v = *(const F4*)(bp + 3 * FF + k);
        acc[0][0] = fma2(a0.lo, b0.lo, acc[0][0]);  acc[0][0] = fma2(a0.hi, b0.hi, acc[0][0]);
        acc[0][1] = fma2(a0.lo, b1.lo, acc[0][1]);  acc[0][1] = fma2(a0.hi, b1.hi, acc[0][1]);
        acc[0][2] = fma2(a0.lo, b2v.lo, acc[0][2]); acc[0][2] = fma2(a0.hi, b2v.hi, acc[0][2]);
        acc[0][3] = fma2(a0.lo, b3v.lo, acc[0][3]); acc[0][3] = fma2(a0.hi, b3v.hi, acc[0][3]);
        acc[1][0] = fma2(a1.lo, b0.lo, acc[1][0]);  acc[1][0] = fma2(a1.hi, b0.hi, acc[1][0]);
        acc[1][1] = fma2(a1.lo, b1.lo, acc[1][1]);  acc[1][1] = fma2(a1.hi, b1.hi, acc[1][1]);
        acc[1][2] = fma2(a1.lo, b2v.lo, acc[1][2]); acc[1][2] = fma2(a1.hi, b2v.hi, acc[1][2]);
        acc[1][3] = fma2(a1.lo, b3v.lo, acc[1][3]); acc[1][3] = fma2(a1.hi, b3v.hi, acc[1][3]);
        acc[2][0] = fma2(a2.lo, b0.lo, acc[2][0]);  acc[2][0] = fma2(a2.hi, b0.hi, acc[2][0]);
        acc[2][1] = fma2(a2.lo, b1.lo, acc[2][1]);  acc[2][1] = fma2(a2.hi, b1.hi, acc[2][1]);
        acc[2][2] = fma2(a2.lo, b2v.lo, acc[2][2]); acc[2][2] = fma2(a2.hi, b2v.hi, acc[2][2]);
        acc[2][3] = fma2(a2.lo, b3v.lo, acc[2][3]); acc[2][3] = fma2(a2.hi, b3v.hi, acc[2][3]);
        acc[3][0] = fma2(a3.lo, b0.lo, acc[3][0]);  acc[3][0] = fma2(a3.hi, b0.hi, acc[3][0]);
        acc[3][1] = fma2(a3.lo, b1.lo, acc[3][1]);  acc[3][1] = fma2(a3.hi, b1.hi, acc[3][1]);
        acc[3][2] = fma2(a3.lo, b2v.lo, acc[3][2]); acc[3][2] = fma2(a3.hi, b2v.hi, acc[3][2]);
        acc[3][3] = fma2(a3.lo, b3v.lo, acc[3][3]); acc[3][3] = fma2(a3.hi, b3v.hi, acc[3][3]);
    }

    #pragma unroll
    for (int ii = 0; ii < 4; ii++) {
        int i = i0 + l + 32 * ii;
        float4 v;
        U64 u0; u0.u = acc[ii][0]; v.x = u0.f.x + u0.f.y;
        U64 u1; u1.u = acc[ii][1]; v.y = u1.f.x + u1.f.y;
        U64 u2; u2.u = acc[ii][2]; v.z = u2.f.x + u2.f.y;
        U64 u3; u3.u = acc[ii][3]; v.w = u3.f.x + u3.f.y;
        if (c0 < MM) *(float4*)&g_pa[i * MM + c0 + 4 * w] = v;
        else         *(float4*)&g_pb[i * MM + (c0 - MM) + 4 * w] = v;
    }
}

// ---------------------------------------------------------------------------
// Pair kernel — EXACT R10 configuration (best measured: 53.2us):
// 32i x 32j tile, 256 threads, 2x2 pairs/thread (rows r, r+16),
// XOR-swizzled smem, weights from __constant__, pipelined m-loop, occ 2.
// ---------------------------------------------------------------------------
#define SMEM_PAIR (2 * TILE * MM * 4)   // 64 KB

__global__ __launch_bounds__(256, 2) void pair_kernel(float* __restrict__ out,
                                                      int has_mask) {
    extern __shared__ float sm[];
    float* sa = sm;                       // 32 x 256, swizzled (pa + cterm)
    float* sb = sm + TILE * MM;           // 32 x 256, swizzled (pb)

    // decode (bi, bj), bi <= bj
    int t = blockIdx.x, bi = 0;
    while (t >= NTILE - bi) { t -= NTILE - bi; bi++; }
    int bj = bi + t;
    int i0 = bi * TILE, j0 = bj * TILE;
    int tid = threadIdx.x;

    // cooperative loads, swizzle on 16B blocks: block q -> q ^ (row & 7)
    for (int u = tid; u < TILE * (MM / 4); u += 256) {
        int r = u >> 6, q = u & 63;
        int dst = r * MM + ((q ^ (r & 7)) << 2);
        float4 va = *(const float4*)&g_pa[(i0 + r) * MM + q * 4];
        float4 ct = *(const float4*)&g_cterm[q * 4];
        va.x += ct.x; va.y += ct.y; va.z += ct.z; va.w += ct.w;
        *(float4*)(sa + dst) = va;
        *(float4*)(sb + dst) = *(const float4*)&g_pb[(j0 + r) * MM + q * 4];
    }
    __syncthreads();

    int ti2 = tid >> 4, tj2 = tid & 15;
    int rA = ti2, rB = ti2 + 16;          // i rows
    int sA = tj2, sB = tj2 + 16;          // j rows
    const char* pa0 = (const char*)(sa + rA * MM);
    const char* pa1 = (const char*)(sa + rB * MM);
    const char* pb0 = (const char*)(sb + sA * MM);
    const char* pb1 = (const char*)(sb + sB * MM);
    unsigned xa0 = (unsigned)(rA & 7) << 4;
    unsigned xa1 = (unsigned)(rB & 7) << 4;
    unsigned xb0 = (unsigned)(sA & 7) << 4;
    unsigned xb1 = (unsigned)(sB & 7) << 4;

    ull acc[4][EE];
    #pragma unroll
    for (int p = 0; p < 4; p++)
        #pragma unroll
        for (int e = 0; e < EE; e++) acc[p][e] = 0ull;

    // prologue: load round 0
    F4 a0 = *(const F4*)(pa0 + (0u ^ xa0));
    F4 a1 = *(const F4*)(pa1 + (0u ^ xa1));
    F4 b0 = *(const F4*)(pb0 + (0u ^ xb0));
    F4 b1 = *(const F4*)(pb1 + (0u ^ xb1));

    #pragma unroll 1
    for (int m = 0; m < MM; m += 4) {
        // prefetch next round (wraps to 0 on last iter — harmless re-read)
        unsigned mn = (unsigned)(((m + 4) & (MM - 1)) << 2);
        F4 na0 = *(const F4*)(pa0 + (mn ^ xa0));
        F4 na1 = *(const F4*)(pa1 + (mn ^ xa1));
        F4 nb0 = *(const F4*)(pb0 + (mn ^ xb0));
        F4 nb1 = *(const F4*)(pb1 + (mn ^ xb1));

        ull rl0 = relu2(add2(a0.lo, b0.lo));
        ull rl1 = relu2(add2(a0.lo, b1.lo));
        ull rl2 = relu2(add2(a1.lo, b0.lo));
        ull rl3 = relu2(add2(a1.lo, b1.lo));
        ull rh0 = relu2(add2(a0.hi, b0.hi));
        ull rh1 = relu2(add2(a0.hi, b1.hi));
        ull rh2 = relu2(add2(a1.hi, b0.hi));
        ull rh3 = relu2(add2(a1.hi, b1.hi));

        #pragma unroll
        for (int e = 0; e < EE; e++) {
            F4 w = *(const F4*)&c_W2f[e * MM + m];   // uniform -> constant port
            acc[0][e] = fma2(rl0, w.lo, acc[0][e]);
            acc[1][e] = fma2(rl1, w.lo, acc[1][e]);
            acc[2][e] = fma2(rl2, w.lo, acc[2][e]);
            acc[3][e] = fma2(rl3, w.lo, acc[3][e]);
            acc[0][e] = fma2(rh0, w.hi, acc[0][e]);
            acc[1][e] = fma2(rh1, w.hi, acc[1][e]);
            acc[2][e] = fma2(rh2, w.hi, acc[2][e]);
            acc[3][e] = fma2(rh3, w.hi, acc[3][e]);
        }

        a0 = na0; a1 = na1; b0 = nb0; b1 = nb1;
    }

    // epilogue (constants from constant memory)
    float vb2[EE], vw3[EE];
    #pragma unroll
    for (int e = 0; e < EE; e++) {
        vb2[e] = c_W2f[EE * MM + e];
        vw3[e] = c_W2f[EE * MM + 8 + e];
    }
    float bb3 = c_W2f[EE * MM + 16];

    int li[4] = { rA, rA, rB, rB };
    int lj[4] = { sA, sB, sA, sB };
    #pragma unroll
    for (int p = 0; p < 4; p++) {
        int i = i0 + li[p], j = j0 + lj[p];
        if (j <= i) continue;
        float z = bb3;
        #pragma unroll
        for (int e = 0; e < EE; e++) {
            U64 u; u.u = acc[p][e];
            float h = u.f.x + u.f.y + vb2[e];
            h = fmaxf(h, 0.0f);
            z = fmaf(h, vw3[e], z);
        }
        float s = 1.0f / (1.0f + expf(-z));
        unsigned pidx = (unsigned)(i * (2 * NN - i - 1) / 2 + (j - i - 1));
        out[pidx] = s;
        if (has_mask) {
            bool msk = (s > 0.5f) && g_stressed[i] && g_stressed[j];
            out[P_TOT + pidx] = msk ? 1.0f : 0.0f;
        }
    }
}

// ---------------------------------------------------------------------------
// Launch: side stream runs stress + prep + weight memcpy, overlapping the
// main-stream gemm. pair waits on both (event fork/join, graph-capturable).
// ---------------------------------------------------------------------------
extern "C" void kernel_launch(void* const* d_in, const int* in_sizes, int n_in,
                              void* d_out, int out_size) {
    const float* x     = (const float*)d_in[0];
    const float* ctx   = (const float*)d_in[1];
    const float* W1    = (const float*)d_in[2];
    const float* b1    = (const float*)d_in[3];
    const float* gamma = (const float*)d_in[4];
    const float* beta  = (const float*)d_in[5];
    const float* rmean = (const float*)d_in[6];
    const float* rvar  = (const float*)d_in[7];
    const float* W2    = (const float*)d_in[8];
    const float* b2    = (const float*)d_in[9];
    const float* W3    = (const float*)d_in[10];
    const float* b3    = (const float*)d_in[11];
    float* out = (float*)d_out;

    (void)in_sizes; (void)n_in;

    static cudaStream_t s1 = 0;
    static cudaEvent_t e0 = 0, e1 = 0;
    static void* w2f_dev = 0;
    if (!s1) {
        cudaStreamCreateWithFlags(&s1, cudaStreamNonBlocking);
        cudaEventCreateWithFlags(&e0, cudaEventDisableTiming);
        cudaEventCreateWithFlags(&e1, cudaEventDisableTiming);
        cudaFuncSetAttribute(pair_kernel,
                             cudaFuncAttributeMaxDynamicSharedMemorySize, SMEM_PAIR);
        cudaGetSymbolAddress(&w2f_dev, g_W2fx);
    }

    // fork: side stream does stress + prep + weight copy while main does gemm
    cudaEventRecord(e0, 0);
    cudaStreamWaitEvent(s1, e0, 0);
    stress_std_kernel<<<NN / 4, 128, 0, s1>>>(x);
    prep_kernel<<<1, MM, 0, s1>>>(ctx, W1, b1, gamma, beta, rmean, rvar,
                                  W2, b2, W3, b3);
    cudaMemcpyToSymbolAsync(c_W2f, w2f_dev, WTOT * sizeof(float),
                            0, cudaMemcpyDeviceToDevice, s1);
    cudaEventRecord(e1, s1);

    gemm_kernel<<<dim3(NN / 128, 512 / 32), 256>>>(x, W1);

    // join
    cudaStreamWaitEvent(0, e1, 0);

    int has_mask = (out_size >= 2 * P_TOT) ? 1 : 0;
    int nblocks = NTILE * (NTILE + 1) / 2;   // 528
    pair_kernel<<<nblocks, 256, SMEM_PAIR>>>(out, has_mask);
}